// round 12
// baseline (speedup 1.0000x reference)
#include <cuda_runtime.h>

#define BATCH 4096
#define SEQL  200
#define NT    500
#define OBS   2
#define LAT   4
#define RNN   25
#define ODEH  20

// Output layout: x_pred [T,B,OBS] | z_traj [T,B,LAT] | z0 [B,LAT] | mu [B,LAT] | logvar [B,LAT]
#define XP_OFF 0
#define ZT_OFF (NT * BATCH * OBS)
#define Z0_OFF (ZT_OFF + NT * BATCH * LAT)
#define MU_OFF (Z0_OFF + BATCH * LAT)
#define LV_OFF (MU_OFF + BATCH * LAT)

typedef unsigned long long ULL;

// ---------- f32x2 packed helpers ----------
__device__ __forceinline__ ULL pack2(float lo, float hi) {
    ULL r; asm("mov.b64 %0, {%1, %2};" : "=l"(r) : "f"(lo), "f"(hi)); return r;
}
__device__ __forceinline__ float2 unpack2(ULL v) {
    float2 r; asm("mov.b64 {%0, %1}, %2;" : "=f"(r.x), "=f"(r.y) : "l"(v)); return r;
}
__device__ __forceinline__ ULL fma2(ULL a, ULL b, ULL c) {
    ULL d; asm("fma.rn.f32x2 %0, %1, %2, %3;" : "=l"(d) : "l"(a), "l"(b), "l"(c)); return d;
}
__device__ __forceinline__ unsigned smem_u32(const void* p) {
    unsigned a;
    asm("{ .reg .u64 t; cvta.to.shared.u64 t, %1; cvt.u32.u64 %0, t; }" : "=r"(a) : "l"(p));
    return a;
}
// un-hoistable shared load (keeps per-chunk weight reloads inside the loop)
__device__ __forceinline__ ULL lds64v(unsigned addr) {
    ULL v; asm volatile("ld.shared.b64 %0, [%1];" : "=l"(v) : "r"(addr)); return v;
}

// ---------- fast transcendentals (exp-based, ~1e-6 rel) ----------
__device__ __forceinline__ float sig_fast(float x) {
    return __fdividef(1.0f, 1.0f + __expf(-x));
}
__device__ __forceinline__ float tanh_fast(float x) {
    float ax = fabsf(x);
    float e  = __expf(-2.0f * ax);
    float t  = __fdividef(1.0f - e, 1.0f + e);
    return copysignf(t, x);
}
__device__ __forceinline__ float elu_fast(float x) {
    float m = fminf(x, 0.0f);
    float e = __expf(m) - 1.0f;
    return e + (x - m);
}

// =====================================================================================
// Kernel 1: single-warp fused reverse GRU. One warp per element alternates
// produce(8-step GI chunk)/consume(8 recurrence steps). Change vs round 11:
// Whh packed columns live in block-shared sWhh, reloaded per chunk (asm volatile LDS)
// so producer/consumer register live-ranges no longer overlap -> (128,4) spill-free.
// =====================================================================================
__global__ void __launch_bounds__(128, 4) gru_fused_kernel(
    const float* __restrict__ obs,
    const float* __restrict__ encW, const float* __restrict__ encB,
    const float* __restrict__ Wih,  const float* __restrict__ bih,
    const float* __restrict__ Whh,  const float* __restrict__ bhh,
    const float* __restrict__ stW,  const float* __restrict__ stB,
    float* __restrict__ out)
{
    __shared__ __align__(16) float sWih[25][76];     // Wih row-major, col 75 = zero pad
    __shared__ __align__(16) ULL   sWhh[14 * 3 * 32]; // [(p*3+g)*32 + lane] packed pairs
    __shared__ __align__(16) float sxp[4][25][12];   // [warp][k][row 0..7 + pad]
    __shared__ __align__(16) float sxg[4][8][76];    // [warp][step-in-chunk][gi column]
    __shared__ __align__(16) float shh[4][2][28];    // [warp][buf][h]

    const int tid  = threadIdx.x;
    const int wid  = tid >> 5;
    const int lane = tid & 31;
    const int b    = blockIdx.x * 4 + wid;
    const int i    = (lane < RNN) ? lane : (RNN - 1);

    // cooperative fill of sWih
    for (int idx = tid; idx < 25 * 76; idx += 128) {
        const int k = idx / 76, j = idx - k * 76;
        sWih[k][j] = (j < 75) ? Wih[k * 75 + j] : 0.f;
    }
    // warp 0 fills sWhh: lane packs its own gate-column i over k-pairs
    if (wid == 0) {
        #pragma unroll
        for (int p = 0; p < 14; p++) {
            const int k0 = 2 * p, k1 = k0 + 1;
            const float r0 = (k0 < RNN) ? Whh[k0 * 75 + i]      : 0.f;
            const float r1 = (k1 < RNN) ? Whh[k1 * 75 + i]      : 0.f;
            const float z0 = (k0 < RNN) ? Whh[k0 * 75 + i + 25] : 0.f;
            const float z1 = (k1 < RNN) ? Whh[k1 * 75 + i + 25] : 0.f;
            const float n0 = (k0 < RNN) ? Whh[k0 * 75 + i + 50] : 0.f;
            const float n1 = (k1 < RNN) ? Whh[k1 * 75 + i + 50] : 0.f;
            sWhh[(p * 3 + 0) * 32 + lane] = pack2(r0, r1);
            sWhh[(p * 3 + 1) * 32 + lane] = pack2(z0, z1);
            sWhh[(p * 3 + 2) * 32 + lane] = pack2(n0, n1);
        }
    }
    __syncthreads();

    // ---- producer per-lane constants ----
    ULL bias[3];
    #pragma unroll
    for (int c = 0; c < 3; c++) {
        const int j = lane + 32 * c;
        bias[c] = (j < 75) ? pack2(bih[j], bih[j]) : 0ULL;
    }
    const int j2 = (lane + 64 < 75) ? (lane + 64) : 75;     // col 75 is zero pad
    const int kk = (lane < 25) ? lane : 0;
    const float e0 = encW[kk], e1 = encW[25 + kk], eb = encB[kk];
    const float2* ob2 = (const float2*)obs + (size_t)b * SEQL;

    const float chr = bhh[i], chz = bhh[25 + i], chn = bhh[50 + i];
    const unsigned whbase = smem_u32(&sWhh[0]) + (unsigned)lane * 8u;

    if (lane < 28) { shh[wid][0][lane] = 0.f; shh[wid][1][lane] = 0.f; }
    __syncwarp();

    float h = 0.f;
    int pbuf = 0;

    #pragma unroll 1
    for (int c = 0; c < 25; c++) {
        // ================= produce chunk c: l = 199-8c-rr, rr = 0..7 =================
        const int l_hi = 199 - 8 * c;
        float2 of2 = make_float2(0.f, 0.f);
        if (lane < 8) of2 = ob2[l_hi - lane];
        #pragma unroll
        for (int rr = 0; rr < 8; rr++) {
            const float o0 = __shfl_sync(0xffffffffu, of2.x, rr);
            const float o1 = __shfl_sync(0xffffffffu, of2.y, rr);
            const float xp = tanh_fast(fmaf(o1, e1, fmaf(o0, e0, eb)));
            if (lane < 25) sxp[wid][lane][rr] = xp;
        }
        __syncwarp();

        ULL acc[3][4];
        #pragma unroll
        for (int cc = 0; cc < 3; cc++)
            #pragma unroll
            for (int pp = 0; pp < 4; pp++) acc[cc][pp] = bias[cc];

        #pragma unroll 5
        for (int k = 0; k < 25; k++) {
            const float4 xa = *(const float4*)&sxp[wid][k][0];   // rows 0..3
            const float4 xb = *(const float4*)&sxp[wid][k][4];   // rows 4..7
            const ULL x01 = pack2(xa.x, xa.y);
            const ULL x23 = pack2(xa.z, xa.w);
            const ULL x45 = pack2(xb.x, xb.y);
            const ULL x67 = pack2(xb.z, xb.w);
            const float w0 = sWih[k][lane];
            const float w1 = sWih[k][lane + 32];
            const float w2 = sWih[k][j2];
            const ULL wk0 = pack2(w0, w0);
            const ULL wk1 = pack2(w1, w1);
            const ULL wk2 = pack2(w2, w2);
            acc[0][0] = fma2(x01, wk0, acc[0][0]);
            acc[0][1] = fma2(x23, wk0, acc[0][1]);
            acc[0][2] = fma2(x45, wk0, acc[0][2]);
            acc[0][3] = fma2(x67, wk0, acc[0][3]);
            acc[1][0] = fma2(x01, wk1, acc[1][0]);
            acc[1][1] = fma2(x23, wk1, acc[1][1]);
            acc[1][2] = fma2(x45, wk1, acc[1][2]);
            acc[1][3] = fma2(x67, wk1, acc[1][3]);
            acc[2][0] = fma2(x01, wk2, acc[2][0]);
            acc[2][1] = fma2(x23, wk2, acc[2][1]);
            acc[2][2] = fma2(x45, wk2, acc[2][2]);
            acc[2][3] = fma2(x67, wk2, acc[2][3]);
        }
        #pragma unroll
        for (int rr = 0; rr < 8; rr++) {
            #pragma unroll
            for (int cc = 0; cc < 3; cc++) {
                const int j = lane + 32 * cc;
                if (j < 75) {
                    const float2 v = unpack2(acc[cc][rr >> 1]);
                    sxg[wid][rr][j] = (rr & 1) ? v.y : v.x;
                }
            }
        }
        __syncwarp();

        // ===== reload consumer weights for this chunk (producer regs now dead) =====
        ULL whr[14], whz[14], whn[14];
        #pragma unroll
        for (int p = 0; p < 14; p++) {
            whr[p] = lds64v(whbase + (unsigned)((p * 3 + 0) * 256));
            whz[p] = lds64v(whbase + (unsigned)((p * 3 + 1) * 256));
            whn[p] = lds64v(whbase + (unsigned)((p * 3 + 2) * 256));
        }

        // ================= consume 8 steps =================
        #pragma unroll
        for (int s = 0; s < 8; s++) {
            const float gir = sxg[wid][s][i];
            const float giz = sxg[wid][s][25 + i];
            const float gin = sxg[wid][s][50 + i];

            const ulonglong2* h4 = (const ulonglong2*)shh[wid][pbuf];
            ULL Ra = 0, Rb = 0, Za = 0, Zb = 0, Na = 0, Nb = 0;
            #pragma unroll
            for (int q = 0; q < 7; q++) {
                const ulonglong2 hv = h4[q];
                Ra = fma2(hv.x, whr[2 * q], Ra);  Rb = fma2(hv.y, whr[2 * q + 1], Rb);
                Za = fma2(hv.x, whz[2 * q], Za);  Zb = fma2(hv.y, whz[2 * q + 1], Zb);
                Na = fma2(hv.x, whn[2 * q], Na);  Nb = fma2(hv.y, whn[2 * q + 1], Nb);
            }
            const float2 ra = unpack2(Ra), rb = unpack2(Rb);
            const float2 za = unpack2(Za), zb = unpack2(Zb);
            const float2 na = unpack2(Na), nb = unpack2(Nb);
            const float ghr = (ra.x + ra.y) + (rb.x + rb.y);
            const float ghz = (za.x + za.y) + (zb.x + zb.y);
            const float ghn = (na.x + na.y) + (nb.x + nb.y);

            const float r  = sig_fast(gir + chr + ghr);
            const float zg = sig_fast(giz + chz + ghz);
            const float n  = tanh_fast(fmaf(r, chn + ghn, gin));
            h = fmaf(zg, h - n, n);

            if (lane < RNN) shh[wid][pbuf ^ 1][lane] = h;
            __syncwarp();
            pbuf ^= 1;
        }
    }

    // stats head: lanes 0..7 -> mu (0..3) / logvar (4..7)
    if (lane < 8) {
        float s = stB[lane];
        #pragma unroll
        for (int k = 0; k < RNN; k++) s = fmaf(shh[wid][pbuf][k], stW[k * 8 + lane], s);
        if (lane < 4) {
            out[Z0_OFF + b * 4 + lane] = s;
            out[MU_OFF + b * 4 + lane] = s;
        } else {
            out[LV_OFF + b * 4 + (lane - 4)] = s;
        }
    }
}

// =====================================================================================
// Kernel 2: dopri5 + FSAL + cubic-Hermite dense output (128 intervals per big step)
// + fused decoder. One warp per block (grid 512) for even SMSP spread.
// 4 lanes/element; lane g owns outputs o = g + 4q.
// =====================================================================================
__device__ __forceinline__ void feval(
    const float (&y)[LAT], float (&k)[LAT],
    const float (&w1)[LAT][5], const float (&b1v)[5],
    const float (&w2)[5][LAT], const float (&b2v)[LAT])
{
    float v[5];
    #pragma unroll
    for (int u = 0; u < 5; u++) {
        float t = b1v[u];
        #pragma unroll
        for (int c = 0; c < LAT; c++) t = fmaf(y[c], w1[c][u], t);
        v[u] = elu_fast(t);
    }
    #pragma unroll
    for (int i = 0; i < LAT; i++) {
        float a  = fmaf(v[0], w2[0][i], v[1] * w2[1][i]);
        float bq = fmaf(v[2], w2[2][i], v[3] * w2[3][i]);
        float s  = fmaf(v[4], w2[4][i], a + bq);
        s += __shfl_xor_sync(0xffffffffu, s, 1);
        s += __shfl_xor_sync(0xffffffffu, s, 2);
        k[i] = s + b2v[i];
    }
}

__device__ __forceinline__ void decode_store(
    const float (&zg)[LAT],
    const float4* __restrict__ sW1, const float2* __restrict__ sW2,
    const float*  __restrict__ sb1, float b20, float b21,
    float* __restrict__ out, int tt, int b)
{
    float x0 = b20, x1 = b21;
    #pragma unroll
    for (int u = 0; u < ODEH; u++) {
        const float4 wv = sW1[u];
        float t = sb1[u];
        t = fmaf(zg[0], wv.x, t);
        t = fmaf(zg[1], wv.y, t);
        t = fmaf(zg[2], wv.z, t);
        t = fmaf(zg[3], wv.w, t);
        t = fmaxf(t, 0.0f);
        const float2 w2v = sW2[u];
        x0 = fmaf(t, w2v.x, x0);
        x1 = fmaf(t, w2v.y, x1);
    }
    float2 ov = {x0, x1};
    *(float2*)(out + XP_OFF + ((size_t)tt * BATCH + b) * 2) = ov;
}

__global__ void __launch_bounds__(32) ode_kernel(
    const float* __restrict__ pt,
    const float* __restrict__ W1,  const float* __restrict__ B1,
    const float* __restrict__ W2,  const float* __restrict__ B2,
    const float* __restrict__ dW1, const float* __restrict__ dB1,
    const float* __restrict__ dW2, const float* __restrict__ dB2,
    float* __restrict__ out)
{
    __shared__ float  spt[NT];
    __shared__ float4 sW1[ODEH];
    __shared__ float2 sW2[ODEH];
    __shared__ float  sb1[ODEH];

    const int tid = threadIdx.x;
    for (int idx = tid; idx < NT; idx += 32) spt[idx] = pt[idx];
    if (tid < ODEH) {
        sW1[tid] = make_float4(dW1[tid], dW1[ODEH + tid], dW1[2 * ODEH + tid], dW1[3 * ODEH + tid]);
        sW2[tid] = make_float2(dW2[tid * 2], dW2[tid * 2 + 1]);
        sb1[tid] = dB1[tid];
    }
    __syncwarp();

    const int gtid = blockIdx.x * 32 + tid;
    const int b    = gtid >> 2;
    const int g    = gtid & 3;
    const float b20 = dB2[0], b21 = dB2[1];

    float w1[LAT][5], b1v[5], w2[5][LAT], b2v[LAT];
    #pragma unroll
    for (int u = 0; u < 5; u++) {
        const int j = g * 5 + u;
        b1v[u] = B1[j];
        #pragma unroll
        for (int c = 0; c < LAT; c++) w1[c][u] = W1[c * ODEH + j];
        #pragma unroll
        for (int i = 0; i < LAT; i++) w2[u][i] = W2[j * LAT + i];
    }
    #pragma unroll
    for (int i = 0; i < LAT; i++) b2v[i] = B2[i];

    const float4 z0v = *(const float4*)(out + Z0_OFF + (size_t)b * 4);
    float z[LAT] = {z0v.x, z0v.y, z0v.z, z0v.w};
    if (g == 0) {
        *(float4*)(out + ZT_OFF + (size_t)b * 4) = z0v;
        decode_store(z, sW1, sW2, sb1, b20, b21, out, 0, b);
    }

    const float A21 = 0.2f;
    const float A31 = 3.0f/40.0f,       A32 = 9.0f/40.0f;
    const float A41 = 44.0f/45.0f,      A42 = -56.0f/15.0f,      A43 = 32.0f/9.0f;
    const float A51 = 19372.0f/6561.0f, A52 = -25360.0f/2187.0f, A53 = 64448.0f/6561.0f, A54 = -212.0f/729.0f;
    const float A61 = 9017.0f/3168.0f,  A62 = -355.0f/33.0f,     A63 = 46732.0f/5247.0f,
                A64 = 49.0f/176.0f,     A65 = -5103.0f/18656.0f;
    const float BB1 = 35.0f/384.0f,     BB3 = 500.0f/1113.0f,    BB4 = 125.0f/192.0f,
                BB5 = -2187.0f/6784.0f, BB6 = 11.0f/84.0f;

    float k1[LAT], k2[LAT], k3[LAT], k4[LAT], k5[LAT], k6[LAT], k7[LAT], y[LAT], z1[LAT];

    feval(z, k1, w1, b1v, w2, b2v);   // initial (FSAL thereafter)

    int m = 0;
    #pragma unroll 1
    for (int grp = 0; grp < 4; ++grp) {
        const int n = (grp < 3) ? 128 : 115;         // 499 = 3*128 + 115
        const float pt0 = spt[m];
        const float h   = spt[m + n] - pt0;

        #pragma unroll
        for (int i = 0; i < LAT; i++) y[i] = fmaf(h, A21 * k1[i], z[i]);
        feval(y, k2, w1, b1v, w2, b2v);
        #pragma unroll
        for (int i = 0; i < LAT; i++) {
            float s = fmaf(A32, k2[i], A31 * k1[i]);
            y[i] = fmaf(h, s, z[i]);
        }
        feval(y, k3, w1, b1v, w2, b2v);
        #pragma unroll
        for (int i = 0; i < LAT; i++) {
            float s = fmaf(A43, k3[i], fmaf(A42, k2[i], A41 * k1[i]));
            y[i] = fmaf(h, s, z[i]);
        }
        feval(y, k4, w1, b1v, w2, b2v);
        #pragma unroll
        for (int i = 0; i < LAT; i++) {
            float s = fmaf(A54, k4[i], fmaf(A53, k3[i], fmaf(A52, k2[i], A51 * k1[i])));
            y[i] = fmaf(h, s, z[i]);
        }
        feval(y, k5, w1, b1v, w2, b2v);
        #pragma unroll
        for (int i = 0; i < LAT; i++) {
            float s = fmaf(A65, k5[i], fmaf(A64, k4[i], fmaf(A63, k3[i], fmaf(A62, k2[i], A61 * k1[i]))));
            y[i] = fmaf(h, s, z[i]);
        }
        feval(y, k6, w1, b1v, w2, b2v);
        #pragma unroll
        for (int i = 0; i < LAT; i++) {
            float s = fmaf(BB6, k6[i], fmaf(BB5, k5[i], fmaf(BB4, k4[i], fmaf(BB3, k3[i], BB1 * k1[i]))));
            z1[i] = fmaf(h, s, z[i]);
        }
        feval(z1, k7, w1, b1v, w2, b2v);  // FSAL: k7 = f(z1) = next k1

        // lane g handles outputs o = g + 4q (o < n); o == n-1 uses exact z1
        #pragma unroll 1
        for (int q = 0; q < 32; q++) {
            const int o = g + q * 4;
            if (o < n) {
                const int tt = m + 1 + o;
                float zg[LAT];
                if (o == n - 1) {
                    #pragma unroll
                    for (int i = 0; i < LAT; i++) zg[i] = z1[i];
                } else {
                    const float s  = __fdividef(spt[tt] - pt0, h);
                    const float s2 = s * s;
                    const float s3 = s2 * s;
                    const float c0 = 2.0f * s3 - 3.0f * s2 + 1.0f;
                    const float c1 = (s3 - 2.0f * s2 + s) * h;
                    const float c2 = 3.0f * s2 - 2.0f * s3;
                    const float c3 = (s3 - s2) * h;
                    #pragma unroll
                    for (int i = 0; i < LAT; i++)
                        zg[i] = fmaf(c3, k7[i], fmaf(c2, z1[i], fmaf(c1, k1[i], c0 * z[i])));
                }
                float4 zo = {zg[0], zg[1], zg[2], zg[3]};
                *(float4*)(out + ZT_OFF + ((size_t)tt * BATCH + b) * 4) = zo;
                decode_store(zg, sW1, sW2, sb1, b20, b21, out, tt, b);
            }
        }

        #pragma unroll
        for (int i = 0; i < LAT; i++) { z[i] = z1[i]; k1[i] = k7[i]; }
        m += n;
    }
}

// =====================================================================================
extern "C" void kernel_launch(void* const* d_in, const int* in_sizes, int n_in,
                              void* d_out, int out_size)
{
    const float* obs   = (const float*)d_in[0];
    const float* pt    = (const float*)d_in[1];
    const float* encW  = (const float*)d_in[2];
    const float* encB  = (const float*)d_in[3];
    const float* Wih   = (const float*)d_in[4];
    const float* Whh   = (const float*)d_in[5];
    const float* bih   = (const float*)d_in[6];
    const float* bhh   = (const float*)d_in[7];
    const float* stW   = (const float*)d_in[8];
    const float* stB   = (const float*)d_in[9];
    const float* oW1   = (const float*)d_in[10];
    const float* ob1   = (const float*)d_in[11];
    const float* oW2   = (const float*)d_in[12];
    const float* ob2   = (const float*)d_in[13];
    const float* dW1   = (const float*)d_in[14];
    const float* db1   = (const float*)d_in[15];
    const float* dW2   = (const float*)d_in[16];
    const float* db2   = (const float*)d_in[17];
    float* out = (float*)d_out;

    gru_fused_kernel<<<BATCH / 4, 128>>>(obs, encW, encB, Wih, bih, Whh, bhh, stW, stB, out);
    ode_kernel<<<(BATCH * 4) / 32, 32>>>(pt, oW1, ob1, oW2, ob2, dW1, db1, dW2, db2, out);
}

// round 13
// speedup vs baseline: 1.0416x; 1.0416x over previous
#include <cuda_runtime.h>

#define BATCH 4096
#define SEQL  200
#define NT    500
#define OBS   2
#define LAT   4
#define RNN   25
#define ODEH  20

// Output layout: x_pred [T,B,OBS] | z_traj [T,B,LAT] | z0 [B,LAT] | mu [B,LAT] | logvar [B,LAT]
#define XP_OFF 0
#define ZT_OFF (NT * BATCH * OBS)
#define Z0_OFF (ZT_OFF + NT * BATCH * LAT)
#define MU_OFF (Z0_OFF + BATCH * LAT)
#define LV_OFF (MU_OFF + BATCH * LAT)

typedef unsigned long long ULL;

// ---------- f32x2 packed helpers ----------
__device__ __forceinline__ ULL pack2(float lo, float hi) {
    ULL r; asm("mov.b64 %0, {%1, %2};" : "=l"(r) : "f"(lo), "f"(hi)); return r;
}
__device__ __forceinline__ float2 unpack2(ULL v) {
    float2 r; asm("mov.b64 {%0, %1}, %2;" : "=f"(r.x), "=f"(r.y) : "l"(v)); return r;
}
__device__ __forceinline__ ULL fma2(ULL a, ULL b, ULL c) {
    ULL d; asm("fma.rn.f32x2 %0, %1, %2, %3;" : "=l"(d) : "l"(a), "l"(b), "l"(c)); return d;
}
__device__ __forceinline__ ULL add2(ULL a, ULL b) {
    ULL d; asm("add.rn.f32x2 %0, %1, %2;" : "=l"(d) : "l"(a), "l"(b)); return d;
}

// ---------- fast transcendentals (exp-based, ~1e-6 rel) ----------
__device__ __forceinline__ float sig_fast(float x) {
    return __fdividef(1.0f, 1.0f + __expf(-x));
}
__device__ __forceinline__ float tanh_fast(float x) {
    float ax = fabsf(x);
    float e  = __expf(-2.0f * ax);
    float t  = __fdividef(1.0f - e, 1.0f + e);
    return copysignf(t, x);
}
// producer-only tanh: input range |x| <~ 6, no sign gymnastics needed
__device__ __forceinline__ float tanh_pe(float x) {
    float e = __expf(-2.0f * x);
    return __fdividef(1.0f - e, 1.0f + e);
}
__device__ __forceinline__ float elu_fast(float x) {
    float m = fminf(x, 0.0f);
    float e = __expf(m) - 1.0f;
    return e + (x - m);
}

// =====================================================================================
// Kernel 1: single-warp fused reverse GRU (round-11 structure: register Whh, (128,3)).
// Trims: bhh_r/bhh_z folded into producer bias; packed-add reduction tree; per-half-
// chunk gi prefetch into registers; cheaper producer tanh.
// =====================================================================================
__global__ void __launch_bounds__(128, 3) gru_fused_kernel(
    const float* __restrict__ obs,
    const float* __restrict__ encW, const float* __restrict__ encB,
    const float* __restrict__ Wih,  const float* __restrict__ bih,
    const float* __restrict__ Whh,  const float* __restrict__ bhh,
    const float* __restrict__ stW,  const float* __restrict__ stB,
    float* __restrict__ out)
{
    __shared__ __align__(16) float sWih[25][76];    // Wih row-major, col 75 = zero pad
    __shared__ __align__(16) float sxp[4][25][12];  // [warp][k][row 0..7 + pad]
    __shared__ __align__(16) float sxg[4][8][76];   // [warp][step-in-chunk][gi column]
    __shared__ __align__(16) float shh[4][2][28];   // [warp][buf][h]

    const int tid  = threadIdx.x;
    const int wid  = tid >> 5;
    const int lane = tid & 31;
    const int b    = blockIdx.x * 4 + wid;
    const int i    = (lane < RNN) ? lane : (RNN - 1);

    // cooperative fill of sWih (uniform barrier once)
    for (int idx = tid; idx < 25 * 76; idx += 128) {
        const int k = idx / 76, j = idx - k * 76;
        sWih[k][j] = (j < 75) ? Wih[k * 75 + j] : 0.f;
    }
    __syncthreads();

    // ---- producer per-lane constants (bias folds bih + bhh for r,z columns) ----
    ULL bias[3];
    #pragma unroll
    for (int c = 0; c < 3; c++) {
        const int j = lane + 32 * c;
        float bv = 0.f;
        if (j < 75) {
            bv = bih[j];
            if (j < 50) bv += bhh[j];       // r,z gate biases folded here
        }
        bias[c] = pack2(bv, bv);
    }
    const int j2 = (lane + 64 < 75) ? (lane + 64) : 75;     // col 75 is zero pad
    const int kk = (lane < 25) ? lane : 0;
    const float e0 = encW[kk], e1 = encW[25 + kk], eb = encB[kk];
    const float2* ob2 = (const float2*)obs + (size_t)b * SEQL;

    // ---- consumer weights: Whh gate-column i packed over k-pairs (registers) ----
    ULL whr[14], whz[14], whn[14];
    #pragma unroll
    for (int p = 0; p < 14; p++) {
        const int k0 = 2 * p, k1 = k0 + 1;
        const float r0 = (k0 < RNN) ? Whh[k0 * 75 + i]      : 0.f;
        const float r1 = (k1 < RNN) ? Whh[k1 * 75 + i]      : 0.f;
        const float z0 = (k0 < RNN) ? Whh[k0 * 75 + i + 25] : 0.f;
        const float z1 = (k1 < RNN) ? Whh[k1 * 75 + i + 25] : 0.f;
        const float n0 = (k0 < RNN) ? Whh[k0 * 75 + i + 50] : 0.f;
        const float n1 = (k1 < RNN) ? Whh[k1 * 75 + i + 50] : 0.f;
        whr[p] = pack2(r0, r1); whz[p] = pack2(z0, z1); whn[p] = pack2(n0, n1);
    }
    const float chn = bhh[50 + i];                  // n-gate hidden bias (inside r*(...))

    if (lane < 28) { shh[wid][0][lane] = 0.f; shh[wid][1][lane] = 0.f; }
    __syncwarp();

    float h = 0.f;
    int pbuf = 0;

    #pragma unroll 1
    for (int c = 0; c < 25; c++) {
        // ================= produce chunk c: l = 199-8c-rr, rr = 0..7 =================
        const int l_hi = 199 - 8 * c;
        float2 of2 = make_float2(0.f, 0.f);
        if (lane < 8) of2 = ob2[l_hi - lane];
        #pragma unroll
        for (int rr = 0; rr < 8; rr++) {
            const float o0 = __shfl_sync(0xffffffffu, of2.x, rr);
            const float o1 = __shfl_sync(0xffffffffu, of2.y, rr);
            const float xp = tanh_pe(fmaf(o1, e1, fmaf(o0, e0, eb)));
            if (lane < 25) sxp[wid][lane][rr] = xp;
        }
        __syncwarp();

        ULL acc[3][4];
        #pragma unroll
        for (int cc = 0; cc < 3; cc++)
            #pragma unroll
            for (int pp = 0; pp < 4; pp++) acc[cc][pp] = bias[cc];

        #pragma unroll 5
        for (int k = 0; k < 25; k++) {
            const float4 xa = *(const float4*)&sxp[wid][k][0];   // rows 0..3
            const float4 xb = *(const float4*)&sxp[wid][k][4];   // rows 4..7
            const ULL x01 = pack2(xa.x, xa.y);
            const ULL x23 = pack2(xa.z, xa.w);
            const ULL x45 = pack2(xb.x, xb.y);
            const ULL x67 = pack2(xb.z, xb.w);
            const float w0 = sWih[k][lane];
            const float w1 = sWih[k][lane + 32];
            const float w2 = sWih[k][j2];
            const ULL wk0 = pack2(w0, w0);
            const ULL wk1 = pack2(w1, w1);
            const ULL wk2 = pack2(w2, w2);
            acc[0][0] = fma2(x01, wk0, acc[0][0]);
            acc[0][1] = fma2(x23, wk0, acc[0][1]);
            acc[0][2] = fma2(x45, wk0, acc[0][2]);
            acc[0][3] = fma2(x67, wk0, acc[0][3]);
            acc[1][0] = fma2(x01, wk1, acc[1][0]);
            acc[1][1] = fma2(x23, wk1, acc[1][1]);
            acc[1][2] = fma2(x45, wk1, acc[1][2]);
            acc[1][3] = fma2(x67, wk1, acc[1][3]);
            acc[2][0] = fma2(x01, wk2, acc[2][0]);
            acc[2][1] = fma2(x23, wk2, acc[2][1]);
            acc[2][2] = fma2(x45, wk2, acc[2][2]);
            acc[2][3] = fma2(x67, wk2, acc[2][3]);
        }
        #pragma unroll
        for (int rr = 0; rr < 8; rr++) {
            #pragma unroll
            for (int cc = 0; cc < 3; cc++) {
                const int j = lane + 32 * cc;
                if (j < 75) {
                    const float2 v = unpack2(acc[cc][rr >> 1]);
                    sxg[wid][rr][j] = (rr & 1) ? v.y : v.x;
                }
            }
        }
        __syncwarp();

        // ================= consume 8 steps (two 4-step halves, gi prefetched) =======
        #pragma unroll
        for (int half = 0; half < 2; half++) {
            float pg0[4], pg1[4], pg2[4];
            #pragma unroll
            for (int s = 0; s < 4; s++) {
                const int ss = half * 4 + s;
                pg0[s] = sxg[wid][ss][i];
                pg1[s] = sxg[wid][ss][25 + i];
                pg2[s] = sxg[wid][ss][50 + i];
            }
            #pragma unroll
            for (int s = 0; s < 4; s++) {
                const ulonglong2* h4 = (const ulonglong2*)shh[wid][pbuf];
                ULL Ra = 0, Rb = 0, Za = 0, Zb = 0, Na = 0, Nb = 0;
                #pragma unroll
                for (int q = 0; q < 7; q++) {
                    const ulonglong2 hv = h4[q];
                    Ra = fma2(hv.x, whr[2 * q], Ra);  Rb = fma2(hv.y, whr[2 * q + 1], Rb);
                    Za = fma2(hv.x, whz[2 * q], Za);  Zb = fma2(hv.y, whz[2 * q + 1], Zb);
                    Na = fma2(hv.x, whn[2 * q], Na);  Nb = fma2(hv.y, whn[2 * q + 1], Nb);
                }
                const float2 rp = unpack2(add2(Ra, Rb));
                const float2 zp = unpack2(add2(Za, Zb));
                const float2 np = unpack2(add2(Na, Nb));

                const float r  = sig_fast(pg0[s] + (rp.x + rp.y));
                const float zg = sig_fast(pg1[s] + (zp.x + zp.y));
                const float n  = tanh_fast(fmaf(r, chn + (np.x + np.y), pg2[s]));
                h = fmaf(zg, h - n, n);

                if (lane < RNN) shh[wid][pbuf ^ 1][lane] = h;
                __syncwarp();
                pbuf ^= 1;
            }
        }
    }

    // stats head: lanes 0..7 -> mu (0..3) / logvar (4..7)
    if (lane < 8) {
        float s = stB[lane];
        #pragma unroll
        for (int k = 0; k < RNN; k++) s = fmaf(shh[wid][pbuf][k], stW[k * 8 + lane], s);
        if (lane < 4) {
            out[Z0_OFF + b * 4 + lane] = s;
            out[MU_OFF + b * 4 + lane] = s;
        } else {
            out[LV_OFF + b * 4 + (lane - 4)] = s;
        }
    }
}

// =====================================================================================
// Kernel 2: dopri5 + FSAL + cubic-Hermite dense output (64 intervals per big step)
// + fused decoder. (Round-11 proven version: 38.5 us.)
// =====================================================================================
__device__ __forceinline__ void feval(
    const float (&y)[LAT], float (&k)[LAT],
    const float (&w1)[LAT][5], const float (&b1v)[5],
    const float (&w2)[5][LAT], const float (&b2v)[LAT])
{
    float v[5];
    #pragma unroll
    for (int u = 0; u < 5; u++) {
        float t = b1v[u];
        #pragma unroll
        for (int c = 0; c < LAT; c++) t = fmaf(y[c], w1[c][u], t);
        v[u] = elu_fast(t);
    }
    #pragma unroll
    for (int i = 0; i < LAT; i++) {
        float a  = fmaf(v[0], w2[0][i], v[1] * w2[1][i]);
        float bq = fmaf(v[2], w2[2][i], v[3] * w2[3][i]);
        float s  = fmaf(v[4], w2[4][i], a + bq);
        s += __shfl_xor_sync(0xffffffffu, s, 1);
        s += __shfl_xor_sync(0xffffffffu, s, 2);
        k[i] = s + b2v[i];
    }
}

__device__ __forceinline__ void decode_store(
    const float (&zg)[LAT],
    const float4* __restrict__ sW1, const float2* __restrict__ sW2,
    const float*  __restrict__ sb1, float b20, float b21,
    float* __restrict__ out, int tt, int b)
{
    float x0 = b20, x1 = b21;
    #pragma unroll
    for (int u = 0; u < ODEH; u++) {
        const float4 wv = sW1[u];
        float t = sb1[u];
        t = fmaf(zg[0], wv.x, t);
        t = fmaf(zg[1], wv.y, t);
        t = fmaf(zg[2], wv.z, t);
        t = fmaf(zg[3], wv.w, t);
        t = fmaxf(t, 0.0f);
        const float2 w2v = sW2[u];
        x0 = fmaf(t, w2v.x, x0);
        x1 = fmaf(t, w2v.y, x1);
    }
    float2 ov = {x0, x1};
    *(float2*)(out + XP_OFF + ((size_t)tt * BATCH + b) * 2) = ov;
}

__global__ void __launch_bounds__(128) ode_kernel(
    const float* __restrict__ pt,
    const float* __restrict__ W1,  const float* __restrict__ B1,
    const float* __restrict__ W2,  const float* __restrict__ B2,
    const float* __restrict__ dW1, const float* __restrict__ dB1,
    const float* __restrict__ dW2, const float* __restrict__ dB2,
    float* __restrict__ out)
{
    __shared__ float  spt[NT];
    __shared__ float4 sW1[ODEH];
    __shared__ float2 sW2[ODEH];
    __shared__ float  sb1[ODEH];

    const int tid = threadIdx.x;
    for (int idx = tid; idx < NT; idx += 128) spt[idx] = pt[idx];
    if (tid < ODEH) {
        sW1[tid] = make_float4(dW1[tid], dW1[ODEH + tid], dW1[2 * ODEH + tid], dW1[3 * ODEH + tid]);
        sW2[tid] = make_float2(dW2[tid * 2], dW2[tid * 2 + 1]);
        sb1[tid] = dB1[tid];
    }
    __syncthreads();

    const int gtid = blockIdx.x * 128 + tid;
    const int b    = gtid >> 2;
    const int g    = gtid & 3;
    const float b20 = dB2[0], b21 = dB2[1];

    float w1[LAT][5], b1v[5], w2[5][LAT], b2v[LAT];
    #pragma unroll
    for (int u = 0; u < 5; u++) {
        const int j = g * 5 + u;
        b1v[u] = B1[j];
        #pragma unroll
        for (int c = 0; c < LAT; c++) w1[c][u] = W1[c * ODEH + j];
        #pragma unroll
        for (int i = 0; i < LAT; i++) w2[u][i] = W2[j * LAT + i];
    }
    #pragma unroll
    for (int i = 0; i < LAT; i++) b2v[i] = B2[i];

    const float4 z0v = *(const float4*)(out + Z0_OFF + (size_t)b * 4);
    float z[LAT] = {z0v.x, z0v.y, z0v.z, z0v.w};
    if (g == 0) {
        *(float4*)(out + ZT_OFF + (size_t)b * 4) = z0v;
        decode_store(z, sW1, sW2, sb1, b20, b21, out, 0, b);
    }

    const float A21 = 0.2f;
    const float A31 = 3.0f/40.0f,       A32 = 9.0f/40.0f;
    const float A41 = 44.0f/45.0f,      A42 = -56.0f/15.0f,      A43 = 32.0f/9.0f;
    const float A51 = 19372.0f/6561.0f, A52 = -25360.0f/2187.0f, A53 = 64448.0f/6561.0f, A54 = -212.0f/729.0f;
    const float A61 = 9017.0f/3168.0f,  A62 = -355.0f/33.0f,     A63 = 46732.0f/5247.0f,
                A64 = 49.0f/176.0f,     A65 = -5103.0f/18656.0f;
    const float BB1 = 35.0f/384.0f,     BB3 = 500.0f/1113.0f,    BB4 = 125.0f/192.0f,
                BB5 = -2187.0f/6784.0f, BB6 = 11.0f/84.0f;

    float k1[LAT], k2[LAT], k3[LAT], k4[LAT], k5[LAT], k6[LAT], k7[LAT], y[LAT], z1[LAT];

    feval(z, k1, w1, b1v, w2, b2v);   // initial (FSAL thereafter)

    int m = 0;
    #pragma unroll 1
    for (int grp = 0; grp < 8; ++grp) {
        const int n = (grp < 7) ? 64 : 51;           // 499 = 7*64 + 51
        const float pt0 = spt[m];
        const float h   = spt[m + n] - pt0;

        #pragma unroll
        for (int i = 0; i < LAT; i++) y[i] = fmaf(h, A21 * k1[i], z[i]);
        feval(y, k2, w1, b1v, w2, b2v);
        #pragma unroll
        for (int i = 0; i < LAT; i++) {
            float s = fmaf(A32, k2[i], A31 * k1[i]);
            y[i] = fmaf(h, s, z[i]);
        }
        feval(y, k3, w1, b1v, w2, b2v);
        #pragma unroll
        for (int i = 0; i < LAT; i++) {
            float s = fmaf(A43, k3[i], fmaf(A42, k2[i], A41 * k1[i]));
            y[i] = fmaf(h, s, z[i]);
        }
        feval(y, k4, w1, b1v, w2, b2v);
        #pragma unroll
        for (int i = 0; i < LAT; i++) {
            float s = fmaf(A54, k4[i], fmaf(A53, k3[i], fmaf(A52, k2[i], A51 * k1[i])));
            y[i] = fmaf(h, s, z[i]);
        }
        feval(y, k5, w1, b1v, w2, b2v);
        #pragma unroll
        for (int i = 0; i < LAT; i++) {
            float s = fmaf(A65, k5[i], fmaf(A64, k4[i], fmaf(A63, k3[i], fmaf(A62, k2[i], A61 * k1[i]))));
            y[i] = fmaf(h, s, z[i]);
        }
        feval(y, k6, w1, b1v, w2, b2v);
        #pragma unroll
        for (int i = 0; i < LAT; i++) {
            float s = fmaf(BB6, k6[i], fmaf(BB5, k5[i], fmaf(BB4, k4[i], fmaf(BB3, k3[i], BB1 * k1[i]))));
            z1[i] = fmaf(h, s, z[i]);
        }
        feval(z1, k7, w1, b1v, w2, b2v);  // FSAL: k7 = f(z1) = next k1

        // lane g handles outputs o = g + 4q (o < n); o == n-1 uses exact z1
        #pragma unroll 1
        for (int q = 0; q < 16; q++) {
            const int o = g + q * 4;
            if (o < n) {
                const int tt = m + 1 + o;
                float zg[LAT];
                if (o == n - 1) {
                    #pragma unroll
                    for (int i = 0; i < LAT; i++) zg[i] = z1[i];
                } else {
                    const float s  = __fdividef(spt[tt] - pt0, h);
                    const float s2 = s * s;
                    const float s3 = s2 * s;
                    const float c0 = 2.0f * s3 - 3.0f * s2 + 1.0f;
                    const float c1 = (s3 - 2.0f * s2 + s) * h;
                    const float c2 = 3.0f * s2 - 2.0f * s3;
                    const float c3 = (s3 - s2) * h;
                    #pragma unroll
                    for (int i = 0; i < LAT; i++)
                        zg[i] = fmaf(c3, k7[i], fmaf(c2, z1[i], fmaf(c1, k1[i], c0 * z[i])));
                }
                float4 zo = {zg[0], zg[1], zg[2], zg[3]};
                *(float4*)(out + ZT_OFF + ((size_t)tt * BATCH + b) * 4) = zo;
                decode_store(zg, sW1, sW2, sb1, b20, b21, out, tt, b);
            }
        }

        #pragma unroll
        for (int i = 0; i < LAT; i++) { z[i] = z1[i]; k1[i] = k7[i]; }
        m += n;
    }
}

// =====================================================================================
extern "C" void kernel_launch(void* const* d_in, const int* in_sizes, int n_in,
                              void* d_out, int out_size)
{
    const float* obs   = (const float*)d_in[0];
    const float* pt    = (const float*)d_in[1];
    const float* encW  = (const float*)d_in[2];
    const float* encB  = (const float*)d_in[3];
    const float* Wih   = (const float*)d_in[4];
    const float* Whh   = (const float*)d_in[5];
    const float* bih   = (const float*)d_in[6];
    const float* bhh   = (const float*)d_in[7];
    const float* stW   = (const float*)d_in[8];
    const float* stB   = (const float*)d_in[9];
    const float* oW1   = (const float*)d_in[10];
    const float* ob1   = (const float*)d_in[11];
    const float* oW2   = (const float*)d_in[12];
    const float* ob2   = (const float*)d_in[13];
    const float* dW1   = (const float*)d_in[14];
    const float* db1   = (const float*)d_in[15];
    const float* dW2   = (const float*)d_in[16];
    const float* db2   = (const float*)d_in[17];
    float* out = (float*)d_out;

    gru_fused_kernel<<<BATCH / 4, 128>>>(obs, encW, encB, Wih, bih, Whh, bhh, stW, stB, out);
    ode_kernel<<<(BATCH * 4) / 128, 128>>>(pt, oW1, ob1, oW2, ob2, dW1, db1, dW2, db2, out);
}

// round 14
// speedup vs baseline: 1.1239x; 1.0790x over previous
#include <cuda_runtime.h>

#define BATCH 4096
#define SEQL  200
#define NT    500
#define OBS   2
#define LAT   4
#define RNN   25
#define ODEH  20

// Output layout: x_pred [T,B,OBS] | z_traj [T,B,LAT] | z0 [B,LAT] | mu [B,LAT] | logvar [B,LAT]
#define XP_OFF 0
#define ZT_OFF (NT * BATCH * OBS)
#define Z0_OFF (ZT_OFF + NT * BATCH * LAT)
#define MU_OFF (Z0_OFF + BATCH * LAT)
#define LV_OFF (MU_OFF + BATCH * LAT)

typedef unsigned long long ULL;

// ---------- f32x2 packed helpers ----------
__device__ __forceinline__ ULL pack2(float lo, float hi) {
    ULL r; asm("mov.b64 %0, {%1, %2};" : "=l"(r) : "f"(lo), "f"(hi)); return r;
}
__device__ __forceinline__ float2 unpack2(ULL v) {
    float2 r; asm("mov.b64 {%0, %1}, %2;" : "=f"(r.x), "=f"(r.y) : "l"(v)); return r;
}
__device__ __forceinline__ ULL fma2(ULL a, ULL b, ULL c) {
    ULL d; asm("fma.rn.f32x2 %0, %1, %2, %3;" : "=l"(d) : "l"(a), "l"(b), "l"(c)); return d;
}
__device__ __forceinline__ float rcp_fast(float x) {
    float r; asm("rcp.approx.ftz.f32 %0, %1;" : "=f"(r) : "f"(x)); return r;
}

// ---------- fast transcendentals ----------
__device__ __forceinline__ float sig_fast(float x) {
    return __fdividef(1.0f, 1.0f + __expf(-x));
}
__device__ __forceinline__ float tanh_fast(float x) {
    float ax = fabsf(x);
    float e  = __expf(-2.0f * ax);
    float t  = (1.0f - e) * rcp_fast(1.0f + e);
    return copysignf(t, x);
}
__device__ __forceinline__ float elu_fast(float x) {
    float m = fminf(x, 0.0f);
    float e = __expf(m) - 1.0f;
    return e + (x - m);
}

// =====================================================================================
// Kernel 1: single-warp fused reverse GRU (round-11 structure, proven). One warp per
// element alternates produce(8-step GI chunk)/consume(8 recurrence steps).
// Changes: shared-reciprocal sigmoid pair in consumer (1 rcp for both gates);
// row-paired tanh reciprocals in producer; r/z biases folded into producer bias.
// =====================================================================================
__global__ void __launch_bounds__(128, 3) gru_fused_kernel(
    const float* __restrict__ obs,
    const float* __restrict__ encW, const float* __restrict__ encB,
    const float* __restrict__ Wih,  const float* __restrict__ bih,
    const float* __restrict__ Whh,  const float* __restrict__ bhh,
    const float* __restrict__ stW,  const float* __restrict__ stB,
    float* __restrict__ out)
{
    __shared__ __align__(16) float sWih[25][76];    // Wih row-major, col 75 = zero pad
    __shared__ __align__(16) float sxp[4][25][12];  // [warp][k][row 0..7 + pad]
    __shared__ __align__(16) float sxg[4][8][76];   // [warp][step-in-chunk][gi column]
    __shared__ __align__(16) float shh[4][2][28];   // [warp][buf][h]

    const int tid  = threadIdx.x;
    const int wid  = tid >> 5;
    const int lane = tid & 31;
    const int b    = blockIdx.x * 4 + wid;
    const int i    = (lane < RNN) ? lane : (RNN - 1);

    // cooperative fill of sWih (uniform barrier once)
    for (int idx = tid; idx < 25 * 76; idx += 128) {
        const int k = idx / 76, j = idx - k * 76;
        sWih[k][j] = (j < 75) ? Wih[k * 75 + j] : 0.f;
    }
    __syncthreads();

    // ---- producer per-lane constants (r,z hidden biases folded in) ----
    ULL bias[3];
    #pragma unroll
    for (int c = 0; c < 3; c++) {
        const int j = lane + 32 * c;
        float bv = 0.f;
        if (j < 75) {
            bv = bih[j];
            if (j < 50) bv += bhh[j];      // r,z gate hidden biases folded here
        }
        bias[c] = pack2(bv, bv);
    }
    const int j2 = (lane + 64 < 75) ? (lane + 64) : 75;     // col 75 is zero pad
    const int kk = (lane < 25) ? lane : 0;
    const float e0 = encW[kk], e1 = encW[25 + kk], eb = encB[kk];
    const float2* ob2 = (const float2*)obs + (size_t)b * SEQL;

    // ---- consumer weights: Whh gate-column i packed over k-pairs (registers) ----
    ULL whr[14], whz[14], whn[14];
    #pragma unroll
    for (int p = 0; p < 14; p++) {
        const int k0 = 2 * p, k1 = k0 + 1;
        const float r0 = (k0 < RNN) ? Whh[k0 * 75 + i]      : 0.f;
        const float r1 = (k1 < RNN) ? Whh[k1 * 75 + i]      : 0.f;
        const float z0 = (k0 < RNN) ? Whh[k0 * 75 + i + 25] : 0.f;
        const float z1 = (k1 < RNN) ? Whh[k1 * 75 + i + 25] : 0.f;
        const float n0 = (k0 < RNN) ? Whh[k0 * 75 + i + 50] : 0.f;
        const float n1 = (k1 < RNN) ? Whh[k1 * 75 + i + 50] : 0.f;
        whr[p] = pack2(r0, r1); whz[p] = pack2(z0, z1); whn[p] = pack2(n0, n1);
    }
    const float chn = bhh[50 + i];                  // n-gate hidden bias

    if (lane < 28) { shh[wid][0][lane] = 0.f; shh[wid][1][lane] = 0.f; }
    __syncwarp();

    float h = 0.f;
    int pbuf = 0;

    #pragma unroll 1
    for (int c = 0; c < 25; c++) {
        // ================= produce chunk c: l = 199-8c-rr, rr = 0..7 =================
        const int l_hi = 199 - 8 * c;
        float2 of2 = make_float2(0.f, 0.f);
        if (lane < 8) of2 = ob2[l_hi - lane];
        #pragma unroll
        for (int rr = 0; rr < 8; rr += 2) {
            const float oa0 = __shfl_sync(0xffffffffu, of2.x, rr);
            const float oa1 = __shfl_sync(0xffffffffu, of2.y, rr);
            const float ob0 = __shfl_sync(0xffffffffu, of2.x, rr + 1);
            const float ob1 = __shfl_sync(0xffffffffu, of2.y, rr + 1);
            // paired tanh: one rcp for two rows (args bounded: |pre| small)
            const float pa = fmaf(oa1, e1, fmaf(oa0, e0, eb));
            const float pb = fmaf(ob1, e1, fmaf(ob0, e0, eb));
            const float ea = __expf(-2.0f * pa);
            const float ebx = __expf(-2.0f * pb);
            const float da = 1.0f + ea, db = 1.0f + ebx;
            const float w  = rcp_fast(da * db);
            const float ta = (1.0f - ea) * db * w;
            const float tb = (1.0f - ebx) * da * w;
            if (lane < 25) { sxp[wid][lane][rr] = ta; sxp[wid][lane][rr + 1] = tb; }
        }
        __syncwarp();

        ULL acc[3][4];
        #pragma unroll
        for (int cc = 0; cc < 3; cc++)
            #pragma unroll
            for (int pp = 0; pp < 4; pp++) acc[cc][pp] = bias[cc];

        #pragma unroll 5
        for (int k = 0; k < 25; k++) {
            const float4 xa = *(const float4*)&sxp[wid][k][0];   // rows 0..3
            const float4 xb = *(const float4*)&sxp[wid][k][4];   // rows 4..7
            const ULL x01 = pack2(xa.x, xa.y);
            const ULL x23 = pack2(xa.z, xa.w);
            const ULL x45 = pack2(xb.x, xb.y);
            const ULL x67 = pack2(xb.z, xb.w);
            const float w0 = sWih[k][lane];
            const float w1 = sWih[k][lane + 32];
            const float w2 = sWih[k][j2];
            const ULL wk0 = pack2(w0, w0);
            const ULL wk1 = pack2(w1, w1);
            const ULL wk2 = pack2(w2, w2);
            acc[0][0] = fma2(x01, wk0, acc[0][0]);
            acc[0][1] = fma2(x23, wk0, acc[0][1]);
            acc[0][2] = fma2(x45, wk0, acc[0][2]);
            acc[0][3] = fma2(x67, wk0, acc[0][3]);
            acc[1][0] = fma2(x01, wk1, acc[1][0]);
            acc[1][1] = fma2(x23, wk1, acc[1][1]);
            acc[1][2] = fma2(x45, wk1, acc[1][2]);
            acc[1][3] = fma2(x67, wk1, acc[1][3]);
            acc[2][0] = fma2(x01, wk2, acc[2][0]);
            acc[2][1] = fma2(x23, wk2, acc[2][1]);
            acc[2][2] = fma2(x45, wk2, acc[2][2]);
            acc[2][3] = fma2(x67, wk2, acc[2][3]);
        }
        #pragma unroll
        for (int rr = 0; rr < 8; rr++) {
            #pragma unroll
            for (int cc = 0; cc < 3; cc++) {
                const int j = lane + 32 * cc;
                if (j < 75) {
                    const float2 v = unpack2(acc[cc][rr >> 1]);
                    sxg[wid][rr][j] = (rr & 1) ? v.y : v.x;
                }
            }
        }
        __syncwarp();

        // ================= consume 8 steps =================
        #pragma unroll
        for (int s = 0; s < 8; s++) {
            const float gir = sxg[wid][s][i];
            const float giz = sxg[wid][s][25 + i];
            const float gin = sxg[wid][s][50 + i];

            const ulonglong2* h4 = (const ulonglong2*)shh[wid][pbuf];
            ULL Ra = 0, Rb = 0, Za = 0, Zb = 0, Na = 0, Nb = 0;
            #pragma unroll
            for (int q = 0; q < 7; q++) {
                const ulonglong2 hv = h4[q];
                Ra = fma2(hv.x, whr[2 * q], Ra);  Rb = fma2(hv.y, whr[2 * q + 1], Rb);
                Za = fma2(hv.x, whz[2 * q], Za);  Zb = fma2(hv.y, whz[2 * q + 1], Zb);
                Na = fma2(hv.x, whn[2 * q], Na);  Nb = fma2(hv.y, whn[2 * q + 1], Nb);
            }
            const float2 ra = unpack2(Ra), rb = unpack2(Rb);
            const float2 za = unpack2(Za), zb = unpack2(Zb);
            const float2 na = unpack2(Na), nb = unpack2(Nb);
            const float aarg = gir + (ra.x + ra.y) + (rb.x + rb.y);
            const float barg = giz + (za.x + za.y) + (zb.x + zb.y);
            const float ghn  = (na.x + na.y) + (nb.x + nb.y);

            // shared-reciprocal sigmoid pair: one rcp for r and zg
            const float ea = __expf(-aarg);
            const float eb2 = __expf(-barg);
            const float da = 1.0f + ea, db = 1.0f + eb2;
            const float w  = rcp_fast(da * db);
            const float r  = db * w;
            const float zg = da * w;

            const float n  = tanh_fast(fmaf(r, chn + ghn, gin));
            h = fmaf(zg, h - n, n);

            if (lane < RNN) shh[wid][pbuf ^ 1][lane] = h;
            __syncwarp();
            pbuf ^= 1;
        }
    }

    // stats head: lanes 0..7 -> mu (0..3) / logvar (4..7)
    if (lane < 8) {
        float s = stB[lane];
        #pragma unroll
        for (int k = 0; k < RNN; k++) s = fmaf(shh[wid][pbuf][k], stW[k * 8 + lane], s);
        if (lane < 4) {
            out[Z0_OFF + b * 4 + lane] = s;
            out[MU_OFF + b * 4 + lane] = s;
        } else {
            out[LV_OFF + b * 4 + (lane - 4)] = s;
        }
    }
}

// =====================================================================================
// Kernel 2: dopri5 + FSAL + cubic-Hermite dense output (64 intervals per big step)
// + fused decoder. (Round-11 proven version: 38.3 us.)
// =====================================================================================
__device__ __forceinline__ void feval(
    const float (&y)[LAT], float (&k)[LAT],
    const float (&w1)[LAT][5], const float (&b1v)[5],
    const float (&w2)[5][LAT], const float (&b2v)[LAT])
{
    float v[5];
    #pragma unroll
    for (int u = 0; u < 5; u++) {
        float t = b1v[u];
        #pragma unroll
        for (int c = 0; c < LAT; c++) t = fmaf(y[c], w1[c][u], t);
        v[u] = elu_fast(t);
    }
    #pragma unroll
    for (int i = 0; i < LAT; i++) {
        float a  = fmaf(v[0], w2[0][i], v[1] * w2[1][i]);
        float bq = fmaf(v[2], w2[2][i], v[3] * w2[3][i]);
        float s  = fmaf(v[4], w2[4][i], a + bq);
        s += __shfl_xor_sync(0xffffffffu, s, 1);
        s += __shfl_xor_sync(0xffffffffu, s, 2);
        k[i] = s + b2v[i];
    }
}

__device__ __forceinline__ void decode_store(
    const float (&zg)[LAT],
    const float4* __restrict__ sW1, const float2* __restrict__ sW2,
    const float*  __restrict__ sb1, float b20, float b21,
    float* __restrict__ out, int tt, int b)
{
    float x0 = b20, x1 = b21;
    #pragma unroll
    for (int u = 0; u < ODEH; u++) {
        const float4 wv = sW1[u];
        float t = sb1[u];
        t = fmaf(zg[0], wv.x, t);
        t = fmaf(zg[1], wv.y, t);
        t = fmaf(zg[2], wv.z, t);
        t = fmaf(zg[3], wv.w, t);
        t = fmaxf(t, 0.0f);
        const float2 w2v = sW2[u];
        x0 = fmaf(t, w2v.x, x0);
        x1 = fmaf(t, w2v.y, x1);
    }
    float2 ov = {x0, x1};
    *(float2*)(out + XP_OFF + ((size_t)tt * BATCH + b) * 2) = ov;
}

__global__ void __launch_bounds__(128) ode_kernel(
    const float* __restrict__ pt,
    const float* __restrict__ W1,  const float* __restrict__ B1,
    const float* __restrict__ W2,  const float* __restrict__ B2,
    const float* __restrict__ dW1, const float* __restrict__ dB1,
    const float* __restrict__ dW2, const float* __restrict__ dB2,
    float* __restrict__ out)
{
    __shared__ float  spt[NT];
    __shared__ float4 sW1[ODEH];
    __shared__ float2 sW2[ODEH];
    __shared__ float  sb1[ODEH];

    const int tid = threadIdx.x;
    for (int idx = tid; idx < NT; idx += 128) spt[idx] = pt[idx];
    if (tid < ODEH) {
        sW1[tid] = make_float4(dW1[tid], dW1[ODEH + tid], dW1[2 * ODEH + tid], dW1[3 * ODEH + tid]);
        sW2[tid] = make_float2(dW2[tid * 2], dW2[tid * 2 + 1]);
        sb1[tid] = dB1[tid];
    }
    __syncthreads();

    const int gtid = blockIdx.x * 128 + tid;
    const int b    = gtid >> 2;
    const int g    = gtid & 3;
    const float b20 = dB2[0], b21 = dB2[1];

    float w1[LAT][5], b1v[5], w2[5][LAT], b2v[LAT];
    #pragma unroll
    for (int u = 0; u < 5; u++) {
        const int j = g * 5 + u;
        b1v[u] = B1[j];
        #pragma unroll
        for (int c = 0; c < LAT; c++) w1[c][u] = W1[c * ODEH + j];
        #pragma unroll
        for (int i = 0; i < LAT; i++) w2[u][i] = W2[j * LAT + i];
    }
    #pragma unroll
    for (int i = 0; i < LAT; i++) b2v[i] = B2[i];

    const float4 z0v = *(const float4*)(out + Z0_OFF + (size_t)b * 4);
    float z[LAT] = {z0v.x, z0v.y, z0v.z, z0v.w};
    if (g == 0) {
        *(float4*)(out + ZT_OFF + (size_t)b * 4) = z0v;
        decode_store(z, sW1, sW2, sb1, b20, b21, out, 0, b);
    }

    const float A21 = 0.2f;
    const float A31 = 3.0f/40.0f,       A32 = 9.0f/40.0f;
    const float A41 = 44.0f/45.0f,      A42 = -56.0f/15.0f,      A43 = 32.0f/9.0f;
    const float A51 = 19372.0f/6561.0f, A52 = -25360.0f/2187.0f, A53 = 64448.0f/6561.0f, A54 = -212.0f/729.0f;
    const float A61 = 9017.0f/3168.0f,  A62 = -355.0f/33.0f,     A63 = 46732.0f/5247.0f,
                A64 = 49.0f/176.0f,     A65 = -5103.0f/18656.0f;
    const float BB1 = 35.0f/384.0f,     BB3 = 500.0f/1113.0f,    BB4 = 125.0f/192.0f,
                BB5 = -2187.0f/6784.0f, BB6 = 11.0f/84.0f;

    float k1[LAT], k2[LAT], k3[LAT], k4[LAT], k5[LAT], k6[LAT], k7[LAT], y[LAT], z1[LAT];

    feval(z, k1, w1, b1v, w2, b2v);   // initial (FSAL thereafter)

    int m = 0;
    #pragma unroll 1
    for (int grp = 0; grp < 8; ++grp) {
        const int n = (grp < 7) ? 64 : 51;           // 499 = 7*64 + 51
        const float pt0 = spt[m];
        const float h   = spt[m + n] - pt0;

        #pragma unroll
        for (int i = 0; i < LAT; i++) y[i] = fmaf(h, A21 * k1[i], z[i]);
        feval(y, k2, w1, b1v, w2, b2v);
        #pragma unroll
        for (int i = 0; i < LAT; i++) {
            float s = fmaf(A32, k2[i], A31 * k1[i]);
            y[i] = fmaf(h, s, z[i]);
        }
        feval(y, k3, w1, b1v, w2, b2v);
        #pragma unroll
        for (int i = 0; i < LAT; i++) {
            float s = fmaf(A43, k3[i], fmaf(A42, k2[i], A41 * k1[i]));
            y[i] = fmaf(h, s, z[i]);
        }
        feval(y, k4, w1, b1v, w2, b2v);
        #pragma unroll
        for (int i = 0; i < LAT; i++) {
            float s = fmaf(A54, k4[i], fmaf(A53, k3[i], fmaf(A52, k2[i], A51 * k1[i])));
            y[i] = fmaf(h, s, z[i]);
        }
        feval(y, k5, w1, b1v, w2, b2v);
        #pragma unroll
        for (int i = 0; i < LAT; i++) {
            float s = fmaf(A65, k5[i], fmaf(A64, k4[i], fmaf(A63, k3[i], fmaf(A62, k2[i], A61 * k1[i]))));
            y[i] = fmaf(h, s, z[i]);
        }
        feval(y, k6, w1, b1v, w2, b2v);
        #pragma unroll
        for (int i = 0; i < LAT; i++) {
            float s = fmaf(BB6, k6[i], fmaf(BB5, k5[i], fmaf(BB4, k4[i], fmaf(BB3, k3[i], BB1 * k1[i]))));
            z1[i] = fmaf(h, s, z[i]);
        }
        feval(z1, k7, w1, b1v, w2, b2v);  // FSAL: k7 = f(z1) = next k1

        // lane g handles outputs o = g + 4q (o < n); o == n-1 uses exact z1
        #pragma unroll 1
        for (int q = 0; q < 16; q++) {
            const int o = g + q * 4;
            if (o < n) {
                const int tt = m + 1 + o;
                float zg[LAT];
                if (o == n - 1) {
                    #pragma unroll
                    for (int i = 0; i < LAT; i++) zg[i] = z1[i];
                } else {
                    const float s  = __fdividef(spt[tt] - pt0, h);
                    const float s2 = s * s;
                    const float s3 = s2 * s;
                    const float c0 = 2.0f * s3 - 3.0f * s2 + 1.0f;
                    const float c1 = (s3 - 2.0f * s2 + s) * h;
                    const float c2 = 3.0f * s2 - 2.0f * s3;
                    const float c3 = (s3 - s2) * h;
                    #pragma unroll
                    for (int i = 0; i < LAT; i++)
                        zg[i] = fmaf(c3, k7[i], fmaf(c2, z1[i], fmaf(c1, k1[i], c0 * z[i])));
                }
                float4 zo = {zg[0], zg[1], zg[2], zg[3]};
                *(float4*)(out + ZT_OFF + ((size_t)tt * BATCH + b) * 4) = zo;
                decode_store(zg, sW1, sW2, sb1, b20, b21, out, tt, b);
            }
        }

        #pragma unroll
        for (int i = 0; i < LAT; i++) { z[i] = z1[i]; k1[i] = k7[i]; }
        m += n;
    }
}

// =====================================================================================
extern "C" void kernel_launch(void* const* d_in, const int* in_sizes, int n_in,
                              void* d_out, int out_size)
{
    const float* obs   = (const float*)d_in[0];
    const float* pt    = (const float*)d_in[1];
    const float* encW  = (const float*)d_in[2];
    const float* encB  = (const float*)d_in[3];
    const float* Wih   = (const float*)d_in[4];
    const float* Whh   = (const float*)d_in[5];
    const float* bih   = (const float*)d_in[6];
    const float* bhh   = (const float*)d_in[7];
    const float* stW   = (const float*)d_in[8];
    const float* stB   = (const float*)d_in[9];
    const float* oW1   = (const float*)d_in[10];
    const float* ob1   = (const float*)d_in[11];
    const float* oW2   = (const float*)d_in[12];
    const float* ob2   = (const float*)d_in[13];
    const float* dW1   = (const float*)d_in[14];
    const float* db1   = (const float*)d_in[15];
    const float* dW2   = (const float*)d_in[16];
    const float* db2   = (const float*)d_in[17];
    float* out = (float*)d_out;

    gru_fused_kernel<<<BATCH / 4, 128>>>(obs, encW, encB, Wih, bih, Whh, bhh, stW, stB, out);
    ode_kernel<<<(BATCH * 4) / 128, 128>>>(pt, oW1, ob1, oW2, ob2, dW1, db1, dW2, db2, out);
}